// round 5
// baseline (speedup 1.0000x reference)
#include <cuda_runtime.h>
#include <cuda_bf16.h>

// ---------------------------------------------------------------------------
// GraphCritic: GCNConv -> per-feature median -> tanh MLP -> scalar
//   - CSR (counting sort) aggregation: no global atomics on feature data,
//     software-pipelined neighbor gather
//   - fp32 GEMM with packed fma.rn.f32x2 + fused per-feature mean/var stats
//   - median via 2x uniform-pivot counting passes (atomic-free private u8
//     counters) + compaction + exact selection on ~600 candidates
// ---------------------------------------------------------------------------

#define NF 128
#define NH 64
#define NMAX 100000
#define EMAX 1600000
#define CAP 32768

__device__ float g_y[NMAX * NF];
__device__ float g_h[NMAX * NF];
__device__ float g_dinv[NMAX];
__device__ int   g_deg[NMAX];
__device__ int   g_rowptr[NMAX];
__device__ int   g_cursor[NMAX];
__device__ int   g_csr[EMAX];
__device__ int   g_bsum[128];
__device__ int   g_boff[128];
__device__ float g_fsum[NF];
__device__ float g_fss[NF];
__device__ float g_L[2][NF];
__device__ float g_IW[2][NF];
__device__ int   g_cnt[32 * NF];
__device__ int   g_bsel[NF];
__device__ int   g_r2[NF];
__device__ int   g_ccnt[NF];
__device__ float g_cand[NF * CAP];
__device__ float g_med[NF];

// ---------------- helpers -------------------------------------------------

__device__ __forceinline__ unsigned long long pack2(float a) {
    unsigned long long r;
    asm("mov.b64 %0, {%1, %1};" : "=l"(r) : "f"(a));
    return r;
}
__device__ __forceinline__ unsigned long long pack2(float a, float b) {
    unsigned long long r;
    asm("mov.b64 %0, {%1, %2};" : "=l"(r) : "f"(a), "f"(b));
    return r;
}
__device__ __forceinline__ void unpack2(unsigned long long v, float& lo, float& hi) {
    asm("mov.b64 {%0, %1}, %2;" : "=f"(lo), "=f"(hi) : "l"(v));
}
__device__ __forceinline__ void fma2(unsigned long long& acc, unsigned long long a,
                                     unsigned long long b) {
    asm("fma.rn.f32x2 %0, %1, %2, %0;" : "+l"(acc) : "l"(a), "l"(b));
}
// monotone bucket map: bucket j (1..30) covers [L+(j-1)W, L+jW), 0 below, 31 above
__device__ __forceinline__ int bucketof(float v, float L, float IW) {
    float t = (v - L) * IW;
    int b = __float2int_rd(t) + 1;
    return max(0, min(31, b));
}

// ---------------- 1) degree / dinv / CSR ----------------------------------

__global__ void k_init(int n) {
    int i = blockIdx.x * blockDim.x + threadIdx.x;
    if (i < n) g_deg[i] = 1;                 // self-loop
    if (i < 32 * NF) g_cnt[i] = 0;
    if (i < NF) { g_fsum[i] = 0.f; g_fss[i] = 0.f; g_ccnt[i] = 0; }
}

__global__ void k_count(const int* __restrict__ dst, int e) {
    int i = blockIdx.x * blockDim.x + threadIdx.x;
    if (i < e) atomicAdd(&g_deg[dst[i]], 1);
}

__global__ void k_dinv(int n) {
    int i = blockIdx.x * blockDim.x + threadIdx.x;
    if (i < n) g_dinv[i] = rsqrtf((float)g_deg[i]);
}

__global__ void k_scan1(int n) {
    __shared__ int sh[1024];
    int gid = blockIdx.x * 1024 + threadIdx.x;
    int val = (gid < n) ? (g_deg[gid] - 1) : 0;
    sh[threadIdx.x] = val;
    __syncthreads();
    for (int off = 1; off < 1024; off <<= 1) {
        int t = (threadIdx.x >= off) ? sh[threadIdx.x - off] : 0;
        __syncthreads();
        sh[threadIdx.x] += t;
        __syncthreads();
    }
    if (gid < n) g_rowptr[gid] = sh[threadIdx.x] - val;   // exclusive (block-local)
    if (threadIdx.x == 1023) g_bsum[blockIdx.x] = sh[1023];
}

__global__ void k_scan2(int nb) {
    __shared__ int sh[1024];
    int val = (threadIdx.x < nb) ? g_bsum[threadIdx.x] : 0;
    sh[threadIdx.x] = val;
    __syncthreads();
    for (int off = 1; off < 1024; off <<= 1) {
        int t = (threadIdx.x >= off) ? sh[threadIdx.x - off] : 0;
        __syncthreads();
        sh[threadIdx.x] += t;
        __syncthreads();
    }
    if (threadIdx.x < nb) g_boff[threadIdx.x] = sh[threadIdx.x] - val;
}

__global__ void k_scan3(int n) {
    int gid = blockIdx.x * blockDim.x + threadIdx.x;
    if (gid < n) {
        int r = g_rowptr[gid] + g_boff[gid >> 10];
        g_rowptr[gid] = r;
        g_cursor[gid] = r;
    }
}

__global__ void k_scatter(const int* __restrict__ src, const int* __restrict__ dst, int e) {
    int i = blockIdx.x * blockDim.x + threadIdx.x;
    if (i < e) {
        int p = atomicAdd(&g_cursor[dst[i]], 1);
        g_csr[p] = src[i];
    }
}

// ---------------- 2) aggregation (warp per node, pipelined CSR gather) ----

__global__ void k_agg(const float4* __restrict__ x4, int n) {
    int w = (blockIdx.x * blockDim.x + threadIdx.x) >> 5;
    if (w >= n) return;
    int lane = threadIdx.x & 31;
    float dv = g_dinv[w];
    float4 acc = __ldg(&x4[w * 32 + lane]);
    float s0 = dv * dv;
    acc.x *= s0; acc.y *= s0; acc.z *= s0; acc.w *= s0;
    int beg = g_rowptr[w];
    int cnt = g_deg[w] - 1;
    if (cnt > 0) {
        // software pipeline: index+dinv of iteration j+1 prefetched during j
        int s = __ldg(&g_csr[beg]);
        float nr = __ldg(&g_dinv[s]) * dv;
        for (int j = 0; j < cnt - 1; j++) {
            int s_nx = __ldg(&g_csr[beg + j + 1]);
            float nr_nx = __ldg(&g_dinv[s_nx]) * dv;
            float4 xv = __ldg(&x4[s * 32 + lane]);
            acc.x += xv.x * nr; acc.y += xv.y * nr;
            acc.z += xv.z * nr; acc.w += xv.w * nr;
            s = s_nx; nr = nr_nx;
        }
        float4 xv = __ldg(&x4[s * 32 + lane]);
        acc.x += xv.x * nr; acc.y += xv.y * nr;
        acc.z += xv.z * nr; acc.w += xv.w * nr;
    }
    ((float4*)g_y)[w * 32 + lane] = acc;
}

// ---------------- 3) GEMM h = y @ W^T + b  (fp32, f32x2) + fused stats ----

#define GEMM_SMEM (128 * 64 * 8 + 64 * 132 * 4)   // 99328 B

__global__ void __launch_bounds__(256, 2)
k_gemm(const float* __restrict__ W, const float* __restrict__ bias, int nrows) {
    extern __shared__ char smraw[];
    unsigned long long* ws2 = (unsigned long long*)smraw;        // [k=128][j2=64]
    float* ys = (float*)(smraw + 128 * 64 * 8);                  // [64][132]
    int tid = threadIdx.x;

    float bf = (tid < NF) ? bias[tid] : 0.f;
    float fsum_l = 0.f, fss_l = 0.f;

    for (int idx = tid; idx < 128 * 64; idx += 256) {
        int j2 = idx & 63, k = idx >> 6;
        ws2[k * 64 + j2] = pack2(W[(2 * j2) * 128 + k], W[(2 * j2 + 1) * 128 + k]);
    }
    __syncthreads();

    int nTiles = (nrows + 63) >> 6;
    int px = tid & 7, ry = tid >> 3;

    for (int tile = blockIdx.x; tile < nTiles; tile += gridDim.x) {
        int row0 = tile << 6;
        for (int i = tid; i < 64 * 32; i += 256) {
            int r = i >> 5, c = i & 31;
            float4 v = (row0 + r < nrows) ? ((const float4*)g_y)[(row0 + r) * 32 + c]
                                          : make_float4(0.f, 0.f, 0.f, 0.f);
            *(float4*)&ys[r * 132 + c * 4] = v;
        }
        __syncthreads();

        unsigned long long acc0[8] = {0,0,0,0,0,0,0,0};
        unsigned long long acc1[8] = {0,0,0,0,0,0,0,0};
        const float* ya = ys + ry * 132;
        const float* yb = ys + (ry + 32) * 132;
        #pragma unroll 8
        for (int k = 0; k < 128; k++) {
            unsigned long long a0 = pack2(ya[k]);
            unsigned long long a1 = pack2(yb[k]);
            const unsigned long long* wk = ws2 + k * 64 + px;
            #pragma unroll
            for (int j = 0; j < 8; j++) {
                unsigned long long w = wk[8 * j];
                fma2(acc0[j], a0, w);
                fma2(acc1[j], a1, w);
            }
        }
        __syncthreads();

        #pragma unroll
        for (int j = 0; j < 8; j++) {
            int col = 2 * (px + 8 * j);
            float lo, hi;
            unpack2(acc0[j], lo, hi);
            ys[ry * 132 + col] = lo; ys[ry * 132 + col + 1] = hi;
            unpack2(acc1[j], lo, hi);
            ys[(ry + 32) * 132 + col] = lo; ys[(ry + 32) * 132 + col + 1] = hi;
        }
        __syncthreads();

        for (int i = tid; i < 64 * 32; i += 256) {
            int r = i >> 5, c = i & 31;
            if (row0 + r < nrows) {
                float4 v = *(float4*)&ys[r * 132 + c * 4];
                float4 b4 = ((const float4*)bias)[c];
                v.x += b4.x; v.y += b4.y; v.z += b4.z; v.w += b4.w;
                ((float4*)g_h)[(row0 + r) * 32 + c] = v;
            }
        }
        // fused per-feature stats (threads 0..127, feature = tid)
        if (tid < NF) {
            int rv = min(64, nrows - row0);
            for (int r = 0; r < rv; r++) {
                float t = ys[r * 132 + tid] + bf;
                fsum_l += t;
                fss_l += t * t;
            }
        }
        __syncthreads();
    }
    if (tid < NF) {
        atomicAdd(&g_fsum[tid], fsum_l);
        atomicAdd(&g_fss[tid], fss_l);
    }
}

// ---------------- 4) median via pivot counting ----------------------------

__global__ void k_piv(float invn) {
    int f = threadIdx.x;
    if (f >= NF) return;
    float m = g_fsum[f] * invn;
    float var = fmaxf(g_fss[f] * invn - m * m, 1e-18f);
    float sd = fmaxf(sqrtf(var), 1e-9f);
    // range mean +- 6 sigma; |mean - median| <= sigma guarantees interior bucket
    g_L[0][f] = m - 6.0f * sd;
    g_IW[0][f] = 2.5f / sd;           // 30 / (12 sigma)
}

// counting pass: per-thread private u8 counters in smem (no atomics in hot loop)
#define CNT_SMEM (1024 * 128)

__global__ void __launch_bounds__(1024, 1) k_cnt(int pass, int nvec) {
    extern __shared__ unsigned char sc[];
    int tid = threadIdx.x;
    for (int i = tid; i < CNT_SMEM / 16; i += 1024)
        ((uint4*)sc)[i] = make_uint4(0u, 0u, 0u, 0u);
    int l = tid & 31, fb = l * 4;
    float L0 = g_L[pass][fb + 0], I0 = g_IW[pass][fb + 0];
    float L1 = g_L[pass][fb + 1], I1 = g_IW[pass][fb + 1];
    float L2 = g_L[pass][fb + 2], I2 = g_IW[pass][fb + 2];
    float L3 = g_L[pass][fb + 3], I3 = g_IW[pass][fb + 3];
    __syncthreads();

    unsigned base = (unsigned)tid << 7;
    int stride = gridDim.x * blockDim.x;   // multiple of 32 -> (i&31) fixed per thread
    for (int i = blockIdx.x * blockDim.x + tid; i < nvec; i += stride) {
        float4 v = ((const float4*)g_h)[i];
        sc[base +  0 + bucketof(v.x, L0, I0)]++;
        sc[base + 32 + bucketof(v.y, L1, I1)]++;
        sc[base + 64 + bucketof(v.z, L2, I2)]++;
        sc[base + 96 + bucketof(v.w, L3, I3)]++;
    }
    __syncthreads();

    for (int p = tid; p < 32 * NF; p += 1024) {
        int b = p >> 7, f = p & 127;
        int q = f & 3, ll = f >> 2;
        int s = 0;
        #pragma unroll 8
        for (int w = 0; w < 32; w++)
            s += sc[(unsigned)((w * 32 + ll) << 7) + (q << 5) + b];
        if (s) atomicAdd(&g_cnt[b * NF + f], s);
    }
}

// per-feature warp: locate rank bucket; phase 0 -> refine pivots, phase 1 -> window
__global__ void k_win(int phase, int rank) {
    int f = (blockIdx.x * blockDim.x + threadIdx.x) >> 5;
    int lane = threadIdx.x & 31;
    if (f >= NF) return;
    int c = g_cnt[lane * NF + f];
    int incl = c;
    #pragma unroll
    for (int d = 1; d < 32; d <<= 1) {
        int t = __shfl_up_sync(0xffffffff, incl, d);
        if (lane >= d) incl += t;
    }
    int excl = incl - c;
    bool found = (excl <= rank) && (rank < incl);
    if (found) {
        if (phase == 0) {
            float L = g_L[0][f], IW = g_IW[0][f];
            float W = 1.0f / IW;
            float lo = L + ((float)lane - 1.1f) * W;   // bucket + safety margin
            float hi = L + ((float)lane + 0.1f) * W;
            g_L[1][f] = lo;
            g_IW[1][f] = 30.0f / (hi - lo);
        } else {
            g_bsel[f] = lane;
            g_r2[f] = rank - excl;
        }
    }
    g_cnt[lane * NF + f] = 0;   // re-arm for next pass
}

__global__ void __launch_bounds__(1024, 1) k_compact(int nvec) {
    int tid = threadIdx.x;
    int l = tid & 31, fb = l * 4;
    float L0 = g_L[1][fb + 0], I0 = g_IW[1][fb + 0]; int b0 = g_bsel[fb + 0];
    float L1 = g_L[1][fb + 1], I1 = g_IW[1][fb + 1]; int b1 = g_bsel[fb + 1];
    float L2 = g_L[1][fb + 2], I2 = g_IW[1][fb + 2]; int b2 = g_bsel[fb + 2];
    float L3 = g_L[1][fb + 3], I3 = g_IW[1][fb + 3]; int b3 = g_bsel[fb + 3];
    int stride = gridDim.x * blockDim.x;
    for (int i = blockIdx.x * blockDim.x + tid; i < nvec; i += stride) {
        float4 v = ((const float4*)g_h)[i];
        if (bucketof(v.x, L0, I0) == b0) {
            int p = atomicAdd(&g_ccnt[fb + 0], 1);
            if (p < CAP) g_cand[(fb + 0) * CAP + p] = v.x;
        }
        if (bucketof(v.y, L1, I1) == b1) {
            int p = atomicAdd(&g_ccnt[fb + 1], 1);
            if (p < CAP) g_cand[(fb + 1) * CAP + p] = v.y;
        }
        if (bucketof(v.z, L2, I2) == b2) {
            int p = atomicAdd(&g_ccnt[fb + 2], 1);
            if (p < CAP) g_cand[(fb + 2) * CAP + p] = v.z;
        }
        if (bucketof(v.w, L3, I3) == b3) {
            int p = atomicAdd(&g_ccnt[fb + 3], 1);
            if (p < CAP) g_cand[(fb + 3) * CAP + p] = v.w;
        }
    }
}

__global__ void k_final() {
    extern __shared__ float scand[];
    int f = blockIdx.x;
    int C = min(g_ccnt[f], CAP);
    for (int i = threadIdx.x; i < C; i += blockDim.x)
        scand[i] = g_cand[f * CAP + i];
    __syncthreads();
    if (C == 0) {
        if (threadIdx.x == 0) g_med[f] = g_L[1][f];
        return;
    }
    int r2 = g_r2[f];
    for (int i = threadIdx.x; i < C; i += blockDim.x) {
        float v = scand[i];
        int less = 0, leq = 0;
        for (int j = 0; j < C; j++) {
            float c = scand[j];
            less += (c < v);
            leq += (c <= v);
        }
        if (less <= r2 && r2 < leq) g_med[f] = v;   // 'lower' k-th smallest
    }
}

// ---------------- 5) MLP ---------------------------------------------------

__global__ void k_mlp(const float* __restrict__ w1, const float* __restrict__ b1,
                      const float* __restrict__ w2, const float* __restrict__ b2,
                      const float* __restrict__ w3, const float* __restrict__ b3,
                      float* __restrict__ out) {
    __shared__ float a1[NH], a2[NH];
    int t = threadIdx.x;
    if (t < NH) {
        float s = b1[t];
        #pragma unroll 4
        for (int f = 0; f < NF; f++) s += g_med[f] * w1[t * NF + f];
        a1[t] = tanhf(s);
    }
    __syncthreads();
    if (t < NH) {
        float s = b2[t];
        #pragma unroll 4
        for (int j = 0; j < NH; j++) s += a1[j] * w2[t * NH + j];
        a2[t] = tanhf(s);
    }
    __syncthreads();
    if (t == 0) {
        float s = b3[0];
        for (int j = 0; j < NH; j++) s += a2[j] * w3[j];
        out[0] = s;
    }
}

// ---------------- launch ---------------------------------------------------

extern "C" void kernel_launch(void* const* d_in, const int* in_sizes, int n_in,
                              void* d_out, int out_size) {
    const float* x  = (const float*)d_in[0];
    const int*   ei = (const int*)d_in[1];
    const float* W  = (const float*)d_in[2];
    const float* cb = (const float*)d_in[3];
    const float* w1 = (const float*)d_in[4];
    const float* b1 = (const float*)d_in[5];
    const float* w2 = (const float*)d_in[6];
    const float* b2 = (const float*)d_in[7];
    const float* w3 = (const float*)d_in[8];
    const float* b3 = (const float*)d_in[9];

    int N = in_sizes[0] / NF;
    int E = in_sizes[1] / 2;
    const int* src = ei;
    const int* dst = ei + E;
    int rank = (N - 1) / 2;
    int nvec = N * (NF / 4);
    int nb = (N + 1023) / 1024;

    // idempotent, called every launch (no static guards allowed)
    cudaFuncSetAttribute(k_gemm, cudaFuncAttributeMaxDynamicSharedMemorySize, GEMM_SMEM);
    cudaFuncSetAttribute(k_cnt, cudaFuncAttributeMaxDynamicSharedMemorySize, CNT_SMEM);
    cudaFuncSetAttribute(k_final, cudaFuncAttributeMaxDynamicSharedMemorySize, CAP * 4);

    k_init<<<(N + 255) / 256, 256>>>(N);
    k_count<<<(E + 255) / 256, 256>>>(dst, E);
    k_dinv<<<(N + 255) / 256, 256>>>(N);
    k_scan1<<<nb, 1024>>>(N);
    k_scan2<<<1, 1024>>>(nb);
    k_scan3<<<(N + 255) / 256, 256>>>(N);
    k_scatter<<<(E + 255) / 256, 256>>>(src, dst, E);
    k_agg<<<(N * 32 + 255) / 256, 256>>>((const float4*)x, N);
    k_gemm<<<296, 256, GEMM_SMEM>>>(W, cb, N);

    k_piv<<<1, 128>>>(1.0f / (float)N);
    k_cnt<<<148, 1024, CNT_SMEM>>>(0, nvec);
    k_win<<<4, 1024>>>(0, rank);
    k_cnt<<<148, 1024, CNT_SMEM>>>(1, nvec);
    k_win<<<4, 1024>>>(1, rank);
    k_compact<<<148, 1024>>>(nvec);
    k_final<<<128, 256, CAP * 4>>>();

    k_mlp<<<1, 128>>>(w1, b1, w2, b2, w3, b3, (float*)d_out);
}

// round 6
// speedup vs baseline: 1.7444x; 1.7444x over previous
#include <cuda_runtime.h>
#include <cuda_bf16.h>

// ---------------------------------------------------------------------------
// GraphCritic: GCNConv -> per-feature median -> tanh MLP -> scalar
//   - CSR (counting sort) aggregation, 2-way pipelined neighbor gather
//   - fp32 GEMM with packed fma.rn.f32x2 + fused per-feature mean/var stats
//   - median via 2x uniform-pivot counting passes with BANK-SWIZZLED private
//     u8 counters (R5 fix: old layout had 32-way smem bank conflicts)
//   - compaction + exact selection on ~600 candidates
// ---------------------------------------------------------------------------

#define NF 128
#define NH 64
#define NMAX 100000
#define EMAX 1600000
#define CAP 32768

__device__ float g_y[NMAX * NF];
__device__ float g_h[NMAX * NF];
__device__ float g_dinv[NMAX];
__device__ int   g_deg[NMAX];
__device__ int   g_rowptr[NMAX];
__device__ int   g_cursor[NMAX];
__device__ int   g_csr[EMAX];
__device__ int   g_bsum[128];
__device__ int   g_boff[128];
__device__ float g_fsum[NF];
__device__ float g_fss[NF];
__device__ float g_L[2][NF];
__device__ float g_IW[2][NF];
__device__ int   g_cnt[32 * NF];
__device__ int   g_bsel[NF];
__device__ int   g_r2[NF];
__device__ int   g_ccnt[NF];
__device__ float g_cand[NF * CAP];
__device__ float g_med[NF];

// ---------------- helpers -------------------------------------------------

__device__ __forceinline__ unsigned long long pack2(float a) {
    unsigned long long r;
    asm("mov.b64 %0, {%1, %1};" : "=l"(r) : "f"(a));
    return r;
}
__device__ __forceinline__ unsigned long long pack2(float a, float b) {
    unsigned long long r;
    asm("mov.b64 %0, {%1, %2};" : "=l"(r) : "f"(a), "f"(b));
    return r;
}
__device__ __forceinline__ void unpack2(unsigned long long v, float& lo, float& hi) {
    asm("mov.b64 {%0, %1}, %2;" : "=f"(lo), "=f"(hi) : "l"(v));
}
__device__ __forceinline__ void fma2(unsigned long long& acc, unsigned long long a,
                                     unsigned long long b) {
    asm("fma.rn.f32x2 %0, %1, %2, %0;" : "+l"(acc) : "l"(a), "l"(b));
}
// monotone bucket map: bucket j (1..30) covers [L+(j-1)W, L+jW), 0 below, 31 above
__device__ __forceinline__ int bucketof(float v, float L, float IW) {
    float t = (v - L) * IW;
    int b = __float2int_rd(t) + 1;
    return max(0, min(31, b));
}

// ---------------- 1) degree / dinv / CSR ----------------------------------

__global__ void k_init(int n) {
    int i = blockIdx.x * blockDim.x + threadIdx.x;
    if (i < n) g_deg[i] = 1;                 // self-loop
    if (i < 32 * NF) g_cnt[i] = 0;
    if (i < NF) { g_fsum[i] = 0.f; g_fss[i] = 0.f; g_ccnt[i] = 0; }
}

__global__ void k_count(const int* __restrict__ dst, int e) {
    int i = blockIdx.x * blockDim.x + threadIdx.x;
    if (i < e) atomicAdd(&g_deg[dst[i]], 1);
}

__global__ void k_dinv(int n) {
    int i = blockIdx.x * blockDim.x + threadIdx.x;
    if (i < n) g_dinv[i] = rsqrtf((float)g_deg[i]);
}

__global__ void k_scan1(int n) {
    __shared__ int sh[1024];
    int gid = blockIdx.x * 1024 + threadIdx.x;
    int val = (gid < n) ? (g_deg[gid] - 1) : 0;
    sh[threadIdx.x] = val;
    __syncthreads();
    for (int off = 1; off < 1024; off <<= 1) {
        int t = (threadIdx.x >= off) ? sh[threadIdx.x - off] : 0;
        __syncthreads();
        sh[threadIdx.x] += t;
        __syncthreads();
    }
    if (gid < n) g_rowptr[gid] = sh[threadIdx.x] - val;   // exclusive (block-local)
    if (threadIdx.x == 1023) g_bsum[blockIdx.x] = sh[1023];
}

__global__ void k_scan2(int nb) {
    __shared__ int sh[1024];
    int val = (threadIdx.x < nb) ? g_bsum[threadIdx.x] : 0;
    sh[threadIdx.x] = val;
    __syncthreads();
    for (int off = 1; off < 1024; off <<= 1) {
        int t = (threadIdx.x >= off) ? sh[threadIdx.x - off] : 0;
        __syncthreads();
        sh[threadIdx.x] += t;
        __syncthreads();
    }
    if (threadIdx.x < nb) g_boff[threadIdx.x] = sh[threadIdx.x] - val;
}

__global__ void k_scan3(int n) {
    int gid = blockIdx.x * blockDim.x + threadIdx.x;
    if (gid < n) {
        int r = g_rowptr[gid] + g_boff[gid >> 10];
        g_rowptr[gid] = r;
        g_cursor[gid] = r;
    }
}

__global__ void k_scatter(const int* __restrict__ src, const int* __restrict__ dst, int e) {
    int i = blockIdx.x * blockDim.x + threadIdx.x;
    if (i < e) {
        int p = atomicAdd(&g_cursor[dst[i]], 1);
        g_csr[p] = src[i];
    }
}

// ---------------- 2) aggregation (warp per node, 2-way pipelined gather) --

__global__ void k_agg(const float4* __restrict__ x4, int n) {
    int w = (blockIdx.x * blockDim.x + threadIdx.x) >> 5;
    if (w >= n) return;
    int lane = threadIdx.x & 31;
    float dv = g_dinv[w];
    float4 acc = __ldg(&x4[w * 32 + lane]);
    float s0 = dv * dv;
    acc.x *= s0; acc.y *= s0; acc.z *= s0; acc.w *= s0;
    float4 acc2 = make_float4(0.f, 0.f, 0.f, 0.f);
    int beg = g_rowptr[w];
    int cnt = g_deg[w] - 1;
    int j = 0;
    for (; j + 2 <= cnt; j += 2) {
        int sa = __ldg(&g_csr[beg + j]);
        int sb = __ldg(&g_csr[beg + j + 1]);
        float na = __ldg(&g_dinv[sa]) * dv;
        float nb = __ldg(&g_dinv[sb]) * dv;
        float4 va = __ldg(&x4[sa * 32 + lane]);
        float4 vb = __ldg(&x4[sb * 32 + lane]);
        acc.x  += va.x * na; acc.y  += va.y * na;
        acc.z  += va.z * na; acc.w  += va.w * na;
        acc2.x += vb.x * nb; acc2.y += vb.y * nb;
        acc2.z += vb.z * nb; acc2.w += vb.w * nb;
    }
    if (j < cnt) {
        int sa = __ldg(&g_csr[beg + j]);
        float na = __ldg(&g_dinv[sa]) * dv;
        float4 va = __ldg(&x4[sa * 32 + lane]);
        acc.x += va.x * na; acc.y += va.y * na;
        acc.z += va.z * na; acc.w += va.w * na;
    }
    acc.x += acc2.x; acc.y += acc2.y; acc.z += acc2.z; acc.w += acc2.w;
    ((float4*)g_y)[w * 32 + lane] = acc;
}

// ---------------- 3) GEMM h = y @ W^T + b  (fp32, f32x2) + fused stats ----

#define GEMM_SMEM (128 * 64 * 8 + 64 * 132 * 4)   // 99328 B

__global__ void __launch_bounds__(256, 2)
k_gemm(const float* __restrict__ W, const float* __restrict__ bias, int nrows) {
    extern __shared__ char smraw[];
    unsigned long long* ws2 = (unsigned long long*)smraw;        // [k=128][j2=64]
    float* ys = (float*)(smraw + 128 * 64 * 8);                  // [64][132]
    int tid = threadIdx.x;

    float bf = (tid < NF) ? bias[tid] : 0.f;
    float fsum_l = 0.f, fss_l = 0.f;

    for (int idx = tid; idx < 128 * 64; idx += 256) {
        int j2 = idx & 63, k = idx >> 6;
        ws2[k * 64 + j2] = pack2(W[(2 * j2) * 128 + k], W[(2 * j2 + 1) * 128 + k]);
    }
    __syncthreads();

    int nTiles = (nrows + 63) >> 6;
    int px = tid & 7, ry = tid >> 3;

    for (int tile = blockIdx.x; tile < nTiles; tile += gridDim.x) {
        int row0 = tile << 6;
        for (int i = tid; i < 64 * 32; i += 256) {
            int r = i >> 5, c = i & 31;
            float4 v = (row0 + r < nrows) ? ((const float4*)g_y)[(row0 + r) * 32 + c]
                                          : make_float4(0.f, 0.f, 0.f, 0.f);
            *(float4*)&ys[r * 132 + c * 4] = v;
        }
        __syncthreads();

        unsigned long long acc0[8] = {0,0,0,0,0,0,0,0};
        unsigned long long acc1[8] = {0,0,0,0,0,0,0,0};
        const float* ya = ys + ry * 132;
        const float* yb = ys + (ry + 32) * 132;
        #pragma unroll 8
        for (int k = 0; k < 128; k++) {
            unsigned long long a0 = pack2(ya[k]);
            unsigned long long a1 = pack2(yb[k]);
            const unsigned long long* wk = ws2 + k * 64 + px;
            #pragma unroll
            for (int j = 0; j < 8; j++) {
                unsigned long long w = wk[8 * j];
                fma2(acc0[j], a0, w);
                fma2(acc1[j], a1, w);
            }
        }
        __syncthreads();

        #pragma unroll
        for (int j = 0; j < 8; j++) {
            int col = 2 * (px + 8 * j);
            float lo, hi;
            unpack2(acc0[j], lo, hi);
            ys[ry * 132 + col] = lo; ys[ry * 132 + col + 1] = hi;
            unpack2(acc1[j], lo, hi);
            ys[(ry + 32) * 132 + col] = lo; ys[(ry + 32) * 132 + col + 1] = hi;
        }
        __syncthreads();

        for (int i = tid; i < 64 * 32; i += 256) {
            int r = i >> 5, c = i & 31;
            if (row0 + r < nrows) {
                float4 v = *(float4*)&ys[r * 132 + c * 4];
                float4 b4 = ((const float4*)bias)[c];
                v.x += b4.x; v.y += b4.y; v.z += b4.z; v.w += b4.w;
                ((float4*)g_h)[(row0 + r) * 32 + c] = v;
            }
        }
        // fused per-feature stats (threads 0..127, feature = tid)
        if (tid < NF) {
            int rv = min(64, nrows - row0);
            for (int r = 0; r < rv; r++) {
                float t = ys[r * 132 + tid] + bf;
                fsum_l += t;
                fss_l += t * t;
            }
        }
        __syncthreads();
    }
    if (tid < NF) {
        atomicAdd(&g_fsum[tid], fsum_l);
        atomicAdd(&g_fss[tid], fss_l);
    }
}

// ---------------- 4) median via pivot counting ----------------------------

__global__ void k_piv(float invn) {
    int f = threadIdx.x;
    if (f >= NF) return;
    float m = g_fsum[f] * invn;
    float var = fmaxf(g_fss[f] * invn - m * m, 1e-18f);
    float sd = fmaxf(sqrtf(var), 1e-9f);
    // range mean +- 6 sigma; |mean - median| <= sigma guarantees interior bucket
    g_L[0][f] = m - 6.0f * sd;
    g_IW[0][f] = 2.5f / sd;           // 30 / (12 sigma)
}

// counting pass: per-thread private u8 counters in smem.
// Counter (q, bucket) of thread tid lives at (tid<<7) + 4*((bucket+lane)&31) + q
// -> bank = (bucket + lane) & 31: distinct per lane for equal buckets,
//    ~uniform for random buckets (R5 fix for 32-way conflicts).
#define CNT_SMEM (1024 * 128)

__global__ void __launch_bounds__(1024, 1) k_cnt(int pass, int nvec) {
    extern __shared__ unsigned char sc[];
    int tid = threadIdx.x;
    for (int i = tid; i < CNT_SMEM / 16; i += 1024)
        ((uint4*)sc)[i] = make_uint4(0u, 0u, 0u, 0u);
    int lane = tid & 31, fb = lane * 4;
    float L0 = g_L[pass][fb + 0], I0 = g_IW[pass][fb + 0];
    float L1 = g_L[pass][fb + 1], I1 = g_IW[pass][fb + 1];
    float L2 = g_L[pass][fb + 2], I2 = g_IW[pass][fb + 2];
    float L3 = g_L[pass][fb + 3], I3 = g_IW[pass][fb + 3];
    __syncthreads();

    unsigned base = (unsigned)tid << 7;
    int stride = gridDim.x * blockDim.x;   // multiple of 32 -> (i&31) fixed per thread
    for (int i = blockIdx.x * blockDim.x + tid; i < nvec; i += stride) {
        float4 v = ((const float4*)g_h)[i];
        int b0 = bucketof(v.x, L0, I0);
        int b1 = bucketof(v.y, L1, I1);
        int b2 = bucketof(v.z, L2, I2);
        int b3 = bucketof(v.w, L3, I3);
        sc[base + 4u * ((b0 + lane) & 31) + 0]++;
        sc[base + 4u * ((b1 + lane) & 31) + 1]++;
        sc[base + 4u * ((b2 + lane) & 31) + 2]++;
        sc[base + 4u * ((b3 + lane) & 31) + 3]++;
    }
    __syncthreads();

    for (int p = tid; p < 32 * NF; p += 1024) {
        int b = p >> 7, f = p & 127;
        int q = f & 3, l = f >> 2;
        unsigned o = 4u * (unsigned)((b + l) & 31) + (unsigned)q;
        int s = 0;
        #pragma unroll 8
        for (int w = 0; w < 32; w++)
            s += sc[(unsigned)((w * 32 + l) << 7) + o];
        if (s) atomicAdd(&g_cnt[b * NF + f], s);
    }
}

// per-feature warp: locate rank bucket; phase 0 -> refine pivots, phase 1 -> window
__global__ void k_win(int phase, int rank) {
    int f = (blockIdx.x * blockDim.x + threadIdx.x) >> 5;
    int lane = threadIdx.x & 31;
    if (f >= NF) return;
    int c = g_cnt[lane * NF + f];
    int incl = c;
    #pragma unroll
    for (int d = 1; d < 32; d <<= 1) {
        int t = __shfl_up_sync(0xffffffff, incl, d);
        if (lane >= d) incl += t;
    }
    int excl = incl - c;
    bool found = (excl <= rank) && (rank < incl);
    if (found) {
        if (phase == 0) {
            float L = g_L[0][f], IW = g_IW[0][f];
            float W = 1.0f / IW;
            float lo = L + ((float)lane - 1.1f) * W;   // bucket + safety margin
            float hi = L + ((float)lane + 0.1f) * W;
            g_L[1][f] = lo;
            g_IW[1][f] = 30.0f / (hi - lo);
        } else {
            g_bsel[f] = lane;
            g_r2[f] = rank - excl;
        }
    }
    g_cnt[lane * NF + f] = 0;   // re-arm for next pass
}

__global__ void __launch_bounds__(1024, 1) k_compact(int nvec) {
    int tid = threadIdx.x;
    int l = tid & 31, fb = l * 4;
    float L0 = g_L[1][fb + 0], I0 = g_IW[1][fb + 0]; int b0 = g_bsel[fb + 0];
    float L1 = g_L[1][fb + 1], I1 = g_IW[1][fb + 1]; int b1 = g_bsel[fb + 1];
    float L2 = g_L[1][fb + 2], I2 = g_IW[1][fb + 2]; int b2 = g_bsel[fb + 2];
    float L3 = g_L[1][fb + 3], I3 = g_IW[1][fb + 3]; int b3 = g_bsel[fb + 3];
    int stride = gridDim.x * blockDim.x;
    for (int i = blockIdx.x * blockDim.x + tid; i < nvec; i += stride) {
        float4 v = ((const float4*)g_h)[i];
        if (bucketof(v.x, L0, I0) == b0) {
            int p = atomicAdd(&g_ccnt[fb + 0], 1);
            if (p < CAP) g_cand[(fb + 0) * CAP + p] = v.x;
        }
        if (bucketof(v.y, L1, I1) == b1) {
            int p = atomicAdd(&g_ccnt[fb + 1], 1);
            if (p < CAP) g_cand[(fb + 1) * CAP + p] = v.y;
        }
        if (bucketof(v.z, L2, I2) == b2) {
            int p = atomicAdd(&g_ccnt[fb + 2], 1);
            if (p < CAP) g_cand[(fb + 2) * CAP + p] = v.z;
        }
        if (bucketof(v.w, L3, I3) == b3) {
            int p = atomicAdd(&g_ccnt[fb + 3], 1);
            if (p < CAP) g_cand[(fb + 3) * CAP + p] = v.w;
        }
    }
}

__global__ void k_final() {
    extern __shared__ float scand[];
    int f = blockIdx.x;
    int C = min(g_ccnt[f], CAP);
    for (int i = threadIdx.x; i < C; i += blockDim.x)
        scand[i] = g_cand[f * CAP + i];
    __syncthreads();
    if (C == 0) {
        if (threadIdx.x == 0) g_med[f] = g_L[1][f];
        return;
    }
    int r2 = g_r2[f];
    for (int i = threadIdx.x; i < C; i += blockDim.x) {
        float v = scand[i];
        int less = 0, leq = 0;
        for (int j = 0; j < C; j++) {
            float c = scand[j];
            less += (c < v);
            leq += (c <= v);
        }
        if (less <= r2 && r2 < leq) g_med[f] = v;   // 'lower' k-th smallest
    }
}

// ---------------- 5) MLP ---------------------------------------------------

__global__ void k_mlp(const float* __restrict__ w1, const float* __restrict__ b1,
                      const float* __restrict__ w2, const float* __restrict__ b2,
                      const float* __restrict__ w3, const float* __restrict__ b3,
                      float* __restrict__ out) {
    __shared__ float a1[NH], a2[NH];
    int t = threadIdx.x;
    if (t < NH) {
        float s = b1[t];
        #pragma unroll 4
        for (int f = 0; f < NF; f++) s += g_med[f] * w1[t * NF + f];
        a1[t] = tanhf(s);
    }
    __syncthreads();
    if (t < NH) {
        float s = b2[t];
        #pragma unroll 4
        for (int j = 0; j < NH; j++) s += a1[j] * w2[t * NH + j];
        a2[t] = tanhf(s);
    }
    __syncthreads();
    if (t == 0) {
        float s = b3[0];
        for (int j = 0; j < NH; j++) s += a2[j] * w3[j];
        out[0] = s;
    }
}

// ---------------- launch ---------------------------------------------------

extern "C" void kernel_launch(void* const* d_in, const int* in_sizes, int n_in,
                              void* d_out, int out_size) {
    const float* x  = (const float*)d_in[0];
    const int*   ei = (const int*)d_in[1];
    const float* W  = (const float*)d_in[2];
    const float* cb = (const float*)d_in[3];
    const float* w1 = (const float*)d_in[4];
    const float* b1 = (const float*)d_in[5];
    const float* w2 = (const float*)d_in[6];
    const float* b2 = (const float*)d_in[7];
    const float* w3 = (const float*)d_in[8];
    const float* b3 = (const float*)d_in[9];

    int N = in_sizes[0] / NF;
    int E = in_sizes[1] / 2;
    const int* src = ei;
    const int* dst = ei + E;
    int rank = (N - 1) / 2;
    int nvec = N * (NF / 4);
    int nb = (N + 1023) / 1024;

    // idempotent, called every launch (no static guards allowed)
    cudaFuncSetAttribute(k_gemm, cudaFuncAttributeMaxDynamicSharedMemorySize, GEMM_SMEM);
    cudaFuncSetAttribute(k_cnt, cudaFuncAttributeMaxDynamicSharedMemorySize, CNT_SMEM);
    cudaFuncSetAttribute(k_final, cudaFuncAttributeMaxDynamicSharedMemorySize, CAP * 4);

    k_init<<<(N + 255) / 256, 256>>>(N);
    k_count<<<(E + 255) / 256, 256>>>(dst, E);
    k_dinv<<<(N + 255) / 256, 256>>>(N);
    k_scan1<<<nb, 1024>>>(N);
    k_scan2<<<1, 1024>>>(nb);
    k_scan3<<<(N + 255) / 256, 256>>>(N);
    k_scatter<<<(E + 255) / 256, 256>>>(src, dst, E);
    k_agg<<<(N * 32 + 255) / 256, 256>>>((const float4*)x, N);
    k_gemm<<<296, 256, GEMM_SMEM>>>(W, cb, N);

    k_piv<<<1, 128>>>(1.0f / (float)N);
    k_cnt<<<148, 1024, CNT_SMEM>>>(0, nvec);
    k_win<<<4, 1024>>>(0, rank);
    k_cnt<<<148, 1024, CNT_SMEM>>>(1, nvec);
    k_win<<<4, 1024>>>(1, rank);
    k_compact<<<148, 1024>>>(nvec);
    k_final<<<128, 256, CAP * 4>>>();

    k_mlp<<<1, 128>>>(w1, b1, w2, b2, w3, b3, (float*)d_out);
}

// round 7
// speedup vs baseline: 1.9732x; 1.1312x over previous
#include <cuda_runtime.h>
#include <cuda_bf16.h>

// ---------------------------------------------------------------------------
// GraphCritic: GCNConv -> per-feature median -> tanh MLP -> scalar
// R7: 3 launches total.
//   A) k_build : init + degree + dinv + scan + CSR scatter + aggregation,
//                fused via software grid barriers (148 CTAs, all resident)
//   B) k_gemm  : fp32 f32x2 GEMM, 128x128 tile, 8x8 thread tile (FMA-bound),
//                direct global epilogue + fused mean/var stats
//   C) k_median: pivots + 2 counting passes + compact + exact select + MLP
// ---------------------------------------------------------------------------

#define NF 128
#define NH 64
#define NMAX 100000
#define EMAX 1600000
#define CAP 32768
#define NBLK 148

__device__ float g_y[NMAX * NF];
__device__ float g_h[NMAX * NF];
__device__ float g_dinv[NMAX];
__device__ int   g_deg[NMAX];
__device__ int   g_rowptr[NMAX];
__device__ int   g_cursor[NMAX];
__device__ int   g_csr[EMAX];
__device__ int   g_bsum[NBLK];
__device__ int   g_boff[NBLK];
__device__ float g_fsum[NF];
__device__ float g_fss[NF];
__device__ float g_L1[NF];
__device__ float g_IW1[NF];
__device__ int   g_cnt[32 * NF];
__device__ int   g_bsel[NF];
__device__ int   g_r2[NF];
__device__ int   g_ccnt[NF];
__device__ float g_cand[NF * CAP];
__device__ float g_med[NF];

// software grid barrier (sense-reversal via generation counter)
__device__ unsigned g_bar_arrive = 0;
__device__ unsigned g_bar_gen = 0;

__device__ __forceinline__ void grid_barrier() {
    __syncthreads();
    if (threadIdx.x == 0) {
        __threadfence();
        unsigned gen = *(volatile unsigned*)&g_bar_gen;
        unsigned t = atomicAdd(&g_bar_arrive, 1u);
        if (t == gridDim.x - 1) {
            g_bar_arrive = 0;
            __threadfence();
            *(volatile unsigned*)&g_bar_gen = gen + 1;
        } else {
            while (*(volatile unsigned*)&g_bar_gen == gen) { __nanosleep(40); }
        }
    }
    __syncthreads();
}

// ---------------- helpers -------------------------------------------------

__device__ __forceinline__ unsigned long long pack2(float a) {
    unsigned long long r;
    asm("mov.b64 %0, {%1, %1};" : "=l"(r) : "f"(a));
    return r;
}
__device__ __forceinline__ unsigned long long pack2(float a, float b) {
    unsigned long long r;
    asm("mov.b64 %0, {%1, %2};" : "=l"(r) : "f"(a), "f"(b));
    return r;
}
__device__ __forceinline__ void unpack2(unsigned long long v, float& lo, float& hi) {
    asm("mov.b64 {%0, %1}, %2;" : "=f"(lo), "=f"(hi) : "l"(v));
}
__device__ __forceinline__ void fma2(unsigned long long& acc, unsigned long long a,
                                     unsigned long long b) {
    asm("fma.rn.f32x2 %0, %1, %2, %0;" : "+l"(acc) : "l"(a), "l"(b));
}
// monotone bucket map: bucket j (1..30) covers [L+(j-1)W, L+jW), 0 below, 31 above
__device__ __forceinline__ int bucketof(float v, float L, float IW) {
    float t = (v - L) * IW;
    int b = __float2int_rd(t) + 1;
    return max(0, min(31, b));
}

// ============================================================================
// Phase A: build (init, degree, dinv, scan, scatter, aggregate)  148 x 1024
// ============================================================================

__global__ void __launch_bounds__(1024, 1)
k_build(const float4* __restrict__ x4, const int* __restrict__ src,
        const int* __restrict__ dst, int n, int e) {
    __shared__ int sh[1024];
    int tid = threadIdx.x;
    int gid = blockIdx.x * 1024 + tid;
    int gsz = gridDim.x * 1024;

    // -- task 1: init
    for (int i = gid; i < n; i += gsz) g_deg[i] = 1;          // self-loop
    for (int i = gid; i < 32 * NF; i += gsz) g_cnt[i] = 0;
    for (int i = gid; i < NF; i += gsz) { g_fsum[i] = 0.f; g_fss[i] = 0.f; g_ccnt[i] = 0; }
    grid_barrier();

    // -- task 2: degree count
    for (int i = gid; i < e; i += gsz) atomicAdd(&g_deg[dst[i]], 1);
    grid_barrier();

    // -- task 3: dinv + exclusive scan of (deg-1)   (n <= gridDim*1024)
    int dval = 0;
    if (gid < n) {
        int d = __ldcg(&g_deg[gid]);   // ldcg: L1 may hold stale deg=1 from task 1
        dval = d - 1;
        g_dinv[gid] = rsqrtf((float)d);
    }
    sh[tid] = dval;
    __syncthreads();
    for (int off = 1; off < 1024; off <<= 1) {
        int t = (tid >= off) ? sh[tid - off] : 0;
        __syncthreads();
        sh[tid] += t;
        __syncthreads();
    }
    int excl = sh[tid] - dval;
    if (tid == 1023) g_bsum[blockIdx.x] = sh[1023];
    grid_barrier();

    if (blockIdx.x == 0) {
        int v = (tid < gridDim.x) ? __ldcg(&g_bsum[tid]) : 0;
        sh[tid] = v;
        __syncthreads();
        for (int off = 1; off < 1024; off <<= 1) {
            int t = (tid >= off) ? sh[tid - off] : 0;
            __syncthreads();
            sh[tid] += t;
            __syncthreads();
        }
        if (tid < gridDim.x) g_boff[tid] = sh[tid] - v;
    }
    grid_barrier();

    if (gid < n) {
        int r = excl + __ldcg(&g_boff[blockIdx.x]);
        g_rowptr[gid] = r;
        g_cursor[gid] = r;
    }
    grid_barrier();

    // -- task 4: scatter edges into CSR buckets
    for (int i = gid; i < e; i += gsz) {
        int p = atomicAdd(&g_cursor[dst[i]], 1);
        g_csr[p] = src[i];
    }
    grid_barrier();

    // -- task 5: aggregation (warp per node, 2-way pipelined gather)
    int lane = tid & 31;
    int wstride = gsz >> 5;
    for (int w = gid >> 5; w < n; w += wstride) {
        float dv = g_dinv[w];
        float4 acc = __ldg(&x4[w * 32 + lane]);
        float s0 = dv * dv;
        acc.x *= s0; acc.y *= s0; acc.z *= s0; acc.w *= s0;
        float4 acc2 = make_float4(0.f, 0.f, 0.f, 0.f);
        int beg = g_rowptr[w];
        int cnt = __ldcg(&g_deg[w]) - 1;
        int j = 0;
        for (; j + 2 <= cnt; j += 2) {
            int sa = __ldg(&g_csr[beg + j]);
            int sb = __ldg(&g_csr[beg + j + 1]);
            float na = __ldg(&g_dinv[sa]) * dv;
            float nb = __ldg(&g_dinv[sb]) * dv;
            float4 va = __ldg(&x4[sa * 32 + lane]);
            float4 vb = __ldg(&x4[sb * 32 + lane]);
            acc.x  += va.x * na; acc.y  += va.y * na;
            acc.z  += va.z * na; acc.w  += va.w * na;
            acc2.x += vb.x * nb; acc2.y += vb.y * nb;
            acc2.z += vb.z * nb; acc2.w += vb.w * nb;
        }
        if (j < cnt) {
            int sa = __ldg(&g_csr[beg + j]);
            float na = __ldg(&g_dinv[sa]) * dv;
            float4 va = __ldg(&x4[sa * 32 + lane]);
            acc.x += va.x * na; acc.y += va.y * na;
            acc.z += va.z * na; acc.w += va.w * na;
        }
        acc.x += acc2.x; acc.y += acc2.y; acc.z += acc2.z; acc.w += acc2.w;
        ((float4*)g_y)[w * 32 + lane] = acc;
    }
}

// ============================================================================
// Phase B: GEMM h = y @ W^T + b,  fused per-feature mean/var stats
//   CTA: 256 threads, tile 128 rows x 128 cols; thread = 8 rows x 8 cols
// ============================================================================

#define GEMM_SMEM (128 * 64 * 8 + 128 * 132 * 4)   // W 65536 + y 67584 = 133120

__global__ void __launch_bounds__(256, 1)
k_gemm(const float* __restrict__ W, const float* __restrict__ bias, int nrows) {
    extern __shared__ char smraw[];
    unsigned long long* ws2 = (unsigned long long*)smraw;        // [k=128][j2=64]
    float* ys = (float*)(smraw + 128 * 64 * 8);                  // [128][132]
    int tid = threadIdx.x;
    int px = tid & 15;          // 16 col groups (4 pairs = 8 cols)
    int ry = tid >> 4;          // 16 row groups (8 rows)
    int px4 = px * 4;

    // pack W: ws2[k][j2] = {W[2j2][k], W[2j2+1][k]}
    for (int idx = tid; idx < 128 * 64; idx += 256) {
        int j2 = idx & 63, k = idx >> 6;
        ws2[k * 64 + j2] = pack2(W[(2 * j2) * 128 + k], W[(2 * j2 + 1) * 128 + k]);
    }

    // bias for this thread's 8 cols
    float4 ba = ((const float4*)bias)[px * 2];
    float4 bb = ((const float4*)bias)[px * 2 + 1];
    float s_sum[8] = {0,0,0,0,0,0,0,0};
    float s_ss[8]  = {0,0,0,0,0,0,0,0};
    __syncthreads();

    int nTiles = (nrows + 127) >> 7;
    for (int tile = blockIdx.x; tile < nTiles; tile += gridDim.x) {
        int row0 = tile << 7;
        // stage y tile [128][128] -> ys pitch 132
        for (int i = tid; i < 128 * 32; i += 256) {
            int r = i >> 5, c = i & 31;
            float4 v = (row0 + r < nrows) ? ((const float4*)g_y)[(row0 + r) * 32 + c]
                                          : make_float4(0.f, 0.f, 0.f, 0.f);
            *(float4*)&ys[r * 132 + c * 4] = v;
        }
        __syncthreads();

        unsigned long long acc[8][4];
        #pragma unroll
        for (int r = 0; r < 8; r++)
            #pragma unroll
            for (int j = 0; j < 4; j++) acc[r][j] = 0ull;

        const float* yb = ys + (ry * 8) * 132;
        #pragma unroll 2
        for (int k = 0; k < 128; k++) {
            ulonglong2 w01 = *(const ulonglong2*)(ws2 + k * 64 + px4);
            ulonglong2 w23 = *(const ulonglong2*)(ws2 + k * 64 + px4 + 2);
            #pragma unroll
            for (int r = 0; r < 8; r++) {
                unsigned long long a = pack2(yb[r * 132 + k]);
                fma2(acc[r][0], a, w01.x);
                fma2(acc[r][1], a, w01.y);
                fma2(acc[r][2], a, w23.x);
                fma2(acc[r][3], a, w23.y);
            }
        }

        // epilogue: bias add, store, stats (no smem round-trip)
        #pragma unroll
        for (int r = 0; r < 8; r++) {
            int rg = row0 + ry * 8 + r;
            if (rg < nrows) {
                float c0, c1, c2, c3, c4, c5, c6, c7;
                unpack2(acc[r][0], c0, c1);
                unpack2(acc[r][1], c2, c3);
                unpack2(acc[r][2], c4, c5);
                unpack2(acc[r][3], c6, c7);
                c0 += ba.x; c1 += ba.y; c2 += ba.z; c3 += ba.w;
                c4 += bb.x; c5 += bb.y; c6 += bb.z; c7 += bb.w;
                float4* out4 = (float4*)g_h + rg * 32 + px * 2;
                out4[0] = make_float4(c0, c1, c2, c3);
                out4[1] = make_float4(c4, c5, c6, c7);
                s_sum[0] += c0; s_ss[0] += c0 * c0;
                s_sum[1] += c1; s_ss[1] += c1 * c1;
                s_sum[2] += c2; s_ss[2] += c2 * c2;
                s_sum[3] += c3; s_ss[3] += c3 * c3;
                s_sum[4] += c4; s_ss[4] += c4 * c4;
                s_sum[5] += c5; s_ss[5] += c5 * c5;
                s_sum[6] += c6; s_ss[6] += c6 * c6;
                s_sum[7] += c7; s_ss[7] += c7 * c7;
            }
        }
        __syncthreads();
    }

    // reduce stats (reuse ys as scratch: 256 floats)
    float* red = ys;
    if (tid < 256) red[tid] = 0.f;
    __syncthreads();
    #pragma unroll
    for (int j = 0; j < 8; j++) {
        atomicAdd(&red[px * 8 + j], s_sum[j]);
        atomicAdd(&red[128 + px * 8 + j], s_ss[j]);
    }
    __syncthreads();
    if (tid < NF) {
        atomicAdd(&g_fsum[tid], red[tid]);
        atomicAdd(&g_fss[tid], red[128 + tid]);
    }
}

// ============================================================================
// Phase C: median (pivots, 2 counting passes, compact, select) + MLP
//   148 x 1024, dynamic smem 128KB (u8 counters / candidate buffer)
// ============================================================================

#define CNT_SMEM (1024 * 128)

__global__ void __launch_bounds__(1024, 1)
k_median(int rank, int nvec, float invn,
         const float* __restrict__ w1, const float* __restrict__ b1,
         const float* __restrict__ w2, const float* __restrict__ b2,
         const float* __restrict__ w3, const float* __restrict__ b3,
         float* __restrict__ out) {
    extern __shared__ unsigned char sc[];
    __shared__ float sL[NF], sIW[NF];
    __shared__ float a1[NH], a2[NH];
    int tid = threadIdx.x;
    int lane = tid & 31;
    int gid = blockIdx.x * 1024 + tid;
    int gsz = gridDim.x * 1024;

    // -- pass-0 pivots from GEMM's mean/var (every block computes its own copy)
    if (tid < NF) {
        float m = __ldcg(&g_fsum[tid]) * invn;
        float var = fmaxf(__ldcg(&g_fss[tid]) * invn - m * m, 1e-18f);
        float sd = fmaxf(sqrtf(var), 1e-9f);
        sL[tid] = m - 6.0f * sd;
        sIW[tid] = 2.5f / sd;          // 30 buckets / 12 sigma
    }

    // ======== counting pass 0 ========
    for (int i = tid; i < CNT_SMEM / 16; i += 1024)
        ((uint4*)sc)[i] = make_uint4(0u, 0u, 0u, 0u);
    __syncthreads();
    {
        int fb = lane * 4;
        float L0 = sL[fb + 0], I0 = sIW[fb + 0];
        float L1 = sL[fb + 1], I1 = sIW[fb + 1];
        float L2 = sL[fb + 2], I2 = sIW[fb + 2];
        float L3 = sL[fb + 3], I3 = sIW[fb + 3];
        unsigned base = (unsigned)tid << 7;
        for (int i = gid; i < nvec; i += gsz) {
            float4 v = ((const float4*)g_h)[i];
            int b0 = bucketof(v.x, L0, I0);
            int b1 = bucketof(v.y, L1, I1);
            int b2 = bucketof(v.z, L2, I2);
            int b3 = bucketof(v.w, L3, I3);
            sc[base + 4u * ((b0 + lane) & 31) + 0]++;
            sc[base + 4u * ((b1 + lane) & 31) + 1]++;
            sc[base + 4u * ((b2 + lane) & 31) + 2]++;
            sc[base + 4u * ((b3 + lane) & 31) + 3]++;
        }
        __syncthreads();
        for (int p = tid; p < 32 * NF; p += 1024) {
            int b = p >> 7, f = p & 127;
            int q = f & 3, l = f >> 2;
            unsigned o = 4u * (unsigned)((b + l) & 31) + (unsigned)q;
            int s = 0;
            #pragma unroll 8
            for (int w = 0; w < 32; w++)
                s += sc[(unsigned)((w * 32 + l) << 7) + o];
            if (s) atomicAdd(&g_cnt[b * NF + f], s);
        }
    }
    grid_barrier();

    // -- window select 0 (blocks 0..3, one warp per feature)
    if (blockIdx.x < 4) {
        int f = blockIdx.x * 32 + (tid >> 5);
        int c = __ldcg(&g_cnt[lane * NF + f]);
        int incl = c;
        #pragma unroll
        for (int d = 1; d < 32; d <<= 1) {
            int t = __shfl_up_sync(0xffffffff, incl, d);
            if (lane >= d) incl += t;
        }
        int excl = incl - c;
        if (excl <= rank && rank < incl) {
            float L = sL[f], IW = sIW[f];
            float Wd = 1.0f / IW;
            float lo = L + ((float)lane - 1.1f) * Wd;   // bucket + safety margin
            float hi = L + ((float)lane + 0.1f) * Wd;
            g_L1[f] = lo;
            g_IW1[f] = 30.0f / (hi - lo);
        }
        g_cnt[lane * NF + f] = 0;   // re-arm
    }
    grid_barrier();

    // ======== counting pass 1 ========
    __syncthreads();
    if (tid < NF) { sL[tid] = __ldcg(&g_L1[tid]); sIW[tid] = __ldcg(&g_IW1[tid]); }
    for (int i = tid; i < CNT_SMEM / 16; i += 1024)
        ((uint4*)sc)[i] = make_uint4(0u, 0u, 0u, 0u);
    __syncthreads();
    {
        int fb = lane * 4;
        float L0 = sL[fb + 0], I0 = sIW[fb + 0];
        float L1 = sL[fb + 1], I1 = sIW[fb + 1];
        float L2 = sL[fb + 2], I2 = sIW[fb + 2];
        float L3 = sL[fb + 3], I3 = sIW[fb + 3];
        unsigned base = (unsigned)tid << 7;
        for (int i = gid; i < nvec; i += gsz) {
            float4 v = ((const float4*)g_h)[i];
            int b0 = bucketof(v.x, L0, I0);
            int b1 = bucketof(v.y, L1, I1);
            int b2 = bucketof(v.z, L2, I2);
            int b3 = bucketof(v.w, L3, I3);
            sc[base + 4u * ((b0 + lane) & 31) + 0]++;
            sc[base + 4u * ((b1 + lane) & 31) + 1]++;
            sc[base + 4u * ((b2 + lane) & 31) + 2]++;
            sc[base + 4u * ((b3 + lane) & 31) + 3]++;
        }
        __syncthreads();
        for (int p = tid; p < 32 * NF; p += 1024) {
            int b = p >> 7, f = p & 127;
            int q = f & 3, l = f >> 2;
            unsigned o = 4u * (unsigned)((b + l) & 31) + (unsigned)q;
            int s = 0;
            #pragma unroll 8
            for (int w = 0; w < 32; w++)
                s += sc[(unsigned)((w * 32 + l) << 7) + o];
            if (s) atomicAdd(&g_cnt[b * NF + f], s);
        }
    }
    grid_barrier();

    // -- window select 1 -> target bucket + residual rank
    if (blockIdx.x < 4) {
        int f = blockIdx.x * 32 + (tid >> 5);
        int c = __ldcg(&g_cnt[lane * NF + f]);
        int incl = c;
        #pragma unroll
        for (int d = 1; d < 32; d <<= 1) {
            int t = __shfl_up_sync(0xffffffff, incl, d);
            if (lane >= d) incl += t;
        }
        int excl = incl - c;
        if (excl <= rank && rank < incl) {
            g_bsel[f] = lane;
            g_r2[f] = rank - excl;
        }
    }
    grid_barrier();

    // ======== compact candidates ========
    {
        int fb = lane * 4;
        float L0 = sL[fb + 0], I0 = sIW[fb + 0]; int b0 = __ldcg(&g_bsel[fb + 0]);
        float L1 = sL[fb + 1], I1 = sIW[fb + 1]; int b1 = __ldcg(&g_bsel[fb + 1]);
        float L2 = sL[fb + 2], I2 = sIW[fb + 2]; int b2 = __ldcg(&g_bsel[fb + 2]);
        float L3 = sL[fb + 3], I3 = sIW[fb + 3]; int b3 = __ldcg(&g_bsel[fb + 3]);
        for (int i = gid; i < nvec; i += gsz) {
            float4 v = ((const float4*)g_h)[i];
            if (bucketof(v.x, L0, I0) == b0) {
                int p = atomicAdd(&g_ccnt[fb + 0], 1);
                if (p < CAP) g_cand[(fb + 0) * CAP + p] = v.x;
            }
            if (bucketof(v.y, L1, I1) == b1) {
                int p = atomicAdd(&g_ccnt[fb + 1], 1);
                if (p < CAP) g_cand[(fb + 1) * CAP + p] = v.y;
            }
            if (bucketof(v.z, L2, I2) == b2) {
                int p = atomicAdd(&g_ccnt[fb + 2], 1);
                if (p < CAP) g_cand[(fb + 2) * CAP + p] = v.z;
            }
            if (bucketof(v.w, L3, I3) == b3) {
                int p = atomicAdd(&g_ccnt[fb + 3], 1);
                if (p < CAP) g_cand[(fb + 3) * CAP + p] = v.w;
            }
        }
    }
    grid_barrier();

    // ======== exact selection (block per feature) ========
    if (blockIdx.x < NF) {
        float* scand = (float*)sc;
        int f = blockIdx.x;
        int C = min(__ldcg(&g_ccnt[f]), CAP);
        for (int i = tid; i < C; i += 1024)
            scand[i] = __ldcg(&g_cand[f * CAP + i]);
        __syncthreads();
        if (C == 0) {
            if (tid == 0) g_med[f] = sL[f];
        } else {
            int r2 = __ldcg(&g_r2[f]);
            for (int i = tid; i < C; i += 1024) {
                float v = scand[i];
                int less = 0, leq = 0;
                for (int j = 0; j < C; j++) {
                    float c = scand[j];
                    less += (c < v);
                    leq += (c <= v);
                }
                if (less <= r2 && r2 < leq) g_med[f] = v;   // 'lower' k-th
            }
        }
    }
    grid_barrier();

    // ======== MLP (block 0) ========
    if (blockIdx.x == 0) {
        if (tid < NH) {
            float s = b1[tid];
            #pragma unroll 4
            for (int f = 0; f < NF; f++) s += __ldcg(&g_med[f]) * w1[tid * NF + f];
            a1[tid] = tanhf(s);
        }
        __syncthreads();
        if (tid < NH) {
            float s = b2[tid];
            #pragma unroll 4
            for (int j = 0; j < NH; j++) s += a1[j] * w2[tid * NH + j];
            a2[tid] = tanhf(s);
        }
        __syncthreads();
        if (tid == 0) {
            float s = b3[0];
            for (int j = 0; j < NH; j++) s += a2[j] * w3[j];
            out[0] = s;
        }
    }
}

// ---------------- launch ---------------------------------------------------

extern "C" void kernel_launch(void* const* d_in, const int* in_sizes, int n_in,
                              void* d_out, int out_size) {
    const float* x  = (const float*)d_in[0];
    const int*   ei = (const int*)d_in[1];
    const float* W  = (const float*)d_in[2];
    const float* cb = (const float*)d_in[3];
    const float* w1 = (const float*)d_in[4];
    const float* b1 = (const float*)d_in[5];
    const float* w2 = (const float*)d_in[6];
    const float* b2 = (const float*)d_in[7];
    const float* w3 = (const float*)d_in[8];
    const float* b3 = (const float*)d_in[9];

    int N = in_sizes[0] / NF;
    int E = in_sizes[1] / 2;
    const int* src = ei;
    const int* dst = ei + E;
    int rank = (N - 1) / 2;
    int nvec = N * (NF / 4);

    cudaFuncSetAttribute(k_gemm, cudaFuncAttributeMaxDynamicSharedMemorySize, GEMM_SMEM);
    cudaFuncSetAttribute(k_median, cudaFuncAttributeMaxDynamicSharedMemorySize, CNT_SMEM);

    k_build<<<NBLK, 1024>>>((const float4*)x, src, dst, N, E);
    k_gemm<<<NBLK, 256, GEMM_SMEM>>>(W, cb, N);
    k_median<<<NBLK, 1024, CNT_SMEM>>>(rank, nvec, 1.0f / (float)N,
                                       w1, b1, w2, b2, w3, b3, (float*)d_out);
}